// round 10
// baseline (speedup 1.0000x reference)
#include <cuda_runtime.h>
#include <cstdint>

#define NB 8
#define NC 19
#define NH 512
#define NW 512
#define HW (NH * NW)            // 262144
#define NPIX (NB * HW)          // 2097152
#define NPAIR (HW / 2)          // 131072 pixel pairs
#define NITERS (NPAIR * NB)     // 1048576 flattened pair-iterations

// g_acc: [0..18] probs_sum_c, [19..37] inter_c, [38] focal [39] nll [40] slp [41] bnll
#define NACC 42

__device__ float g_acc[NACC];
__device__ int g_cnt[NC];
__device__ unsigned int g_ticket;
__device__ unsigned char g_diff[HW];

// ---------------------------------------------------------------------------
#define DB 128
#define DG ((HW / 4) / DB)      // 512 blocks

__global__ __launch_bounds__(DB) void diff_kernel(const int* __restrict__ tgt) {
    __shared__ unsigned int s_h[DB][NC];
#pragma unroll
    for (int c = 0; c < NC; c++) s_h[threadIdx.x][c] = 0u;

    const int idx = blockIdx.x * DB + threadIdx.x;      // over HW/4
    const int h = idx >> 7;
    const bool interior = (h >= 1) && (h <= NH - 2);
    const int4* t4 = (const int4*)tgt;

    uchar4 d = make_uchar4(0, 0, 0, 0);
#pragma unroll
    for (int b = 0; b < NB; b++) {
        int base = b * (HW / 4) + idx;
        int4 m = __ldg(t4 + base);
        s_h[threadIdx.x][m.x]++;
        s_h[threadIdx.x][m.y]++;
        s_h[threadIdx.x][m.z]++;
        s_h[threadIdx.x][m.w]++;
        if (interior) {
            int4 a = __ldg(t4 + base - NW / 4);
            int4 q = __ldg(t4 + base + NW / 4);
            d.x |= (unsigned char)((a.x != m.x) | (a.x != q.x));
            d.y |= (unsigned char)((a.y != m.y) | (a.y != q.y));
            d.z |= (unsigned char)((a.z != m.z) | (a.z != q.z));
            d.w |= (unsigned char)((a.w != m.w) | (a.w != q.w));
        }
    }
    ((uchar4*)g_diff)[idx] = d;

    __syncthreads();
    if (threadIdx.x < NC) {
        unsigned int s = 0;
#pragma unroll 8
        for (int r = 0; r < DB; r++) s += s_h[r][threadIdx.x];
        atomicAdd(&g_cnt[threadIdx.x], (int)s);
    }
}

// ---------------------------------------------------------------------------
__device__ __forceinline__ float warp_sum(float v) {
#pragma unroll
    for (int o = 16; o; o >>= 1) v += __shfl_down_sync(0xffffffffu, v, o);
    return v;
}

// ---------------------------------------------------------------------------
// Persistent, software-pipelined main kernel.
#define MBT 128                      // threads per block
#define MAIN_BLOCKS 444              // 3 CTAs/SM * 148 SMs, single wave
#define NTH (MAIN_BLOCKS * MBT)      // 56832 threads
#define FULL_ROUNDS 18               // guaranteed rounds per thread
// 18*56832 = 1022976; remainder 25600 handled by tid < 25600 in round 18.

struct Batch {
    float2 x[NC];
    int2 tt;
};

__device__ __forceinline__ void load_batch(const float2* __restrict__ in2,
                                           const int2* __restrict__ tgt2,
                                           int idx, Batch& B) {
    const int pair = idx & (NPAIR - 1);
    const int b = idx >> 17;                     // NPAIR == 2^17
    const float2* base = in2 + (size_t)b * (NC * (HW / 2)) + pair;
    B.tt = __ldg(tgt2 + b * (HW / 2) + pair);
#pragma unroll
    for (int c = 0; c < NC; c++) B.x[c] = __ldg(base + (size_t)c * (HW / 2));
}

__device__ __forceinline__ void compute_batch(
    Batch& B, int idx, int wid, float (*s_int)[NC],
    float (&denom)[NC], float& a_focal, float& a_nll, float& a_slp, float& a_bnll)
{
    const int pair = idx & (NPAIR - 1);
    const int t0 = B.tt.x, t1 = B.tt.y;

    // boundary flags (g_diff is 256 KB, L2-resident)
    const int hw0 = 2 * pair;
    const int h = hw0 >> 9;
    const int w0 = hw0 & (NW - 1);
    float bm0 = 0.0f, bm1 = 0.0f;
    if (h >= 1 && h <= NH - 2) {
        unsigned char dm = g_diff[hw0];
        unsigned char dp = g_diff[hw0 + 1];
        if (w0 >= 1) bm0 = (float)(g_diff[hw0 - 1] | dm | dp);
        if (w0 + 1 <= NW - 2) bm1 = (float)(dm | dp | g_diff[hw0 + 2]);
    }

    // target select + raw sums
    float xt0 = 0.0f, xt1 = 0.0f;
    float sA0 = 0.f, sB0 = 0.f, sA1 = 0.f, sB1 = 0.f;
#pragma unroll
    for (int c = 0; c < NC; c++) {
        float vx = B.x[c].x, vy = B.x[c].y;
        xt0 = (c == t0) ? vx : xt0;
        xt1 = (c == t1) ? vy : xt1;
        if (c & 1) { sB0 += vx; sB1 += vy; }
        else       { sA0 += vx; sA1 += vy; }
    }
    const float sumx0 = sA0 + sB0, sumx1 = sA1 + sB1;

    // exponentials + partition functions (in-place; consumes the buffer)
    float zA0 = 0.f, zB0 = 0.f, zA1 = 0.f, zB1 = 0.f;
#pragma unroll
    for (int c = 0; c < NC; c++) {
        float ex = __expf(B.x[c].x);
        float ey = __expf(B.x[c].y);
        if (c & 1) { zB0 += ex; zB1 += ey; }
        else       { zA0 += ex; zA1 += ey; }
        B.x[c].x = ex; B.x[c].y = ey;
    }
    const float Z0 = zA0 + zB0, Z1 = zA1 + zB1;

    const float invZ0 = __fdividef(1.0f, Z0);
    const float invZ1 = __fdividef(1.0f, Z1);
    const float logZ0 = __logf(Z0);
    const float logZ1 = __logf(Z1);
    const float nll0 = logZ0 - xt0;
    const float nll1 = logZ1 - xt1;
    const float pt0 = __expf(xt0) * invZ0;
    const float pt1 = __expf(xt1) * invZ1;

#pragma unroll
    for (int c = 0; c < NC; c++) {
        denom[c] = fmaf(B.x[c].x, invZ0, fmaf(B.x[c].y, invZ1, denom[c]));
    }

    const float om0 = 1.0f - pt0, om1 = 1.0f - pt1;
    a_focal = fmaf(om0 * om0, nll0, fmaf(om1 * om1, nll1, a_focal));
    a_nll += nll0 + nll1;
    a_slp += (sumx0 + sumx1) - (float)NC * (logZ0 + logZ1);
    a_bnll = fmaf(nll0, bm0, fmaf(nll1, bm1, a_bnll));

    atomicAdd(&s_int[wid][t0], pt0);
    atomicAdd(&s_int[wid][t1], pt1);
}

__global__ __launch_bounds__(MBT, 3) void main_kernel(const float* __restrict__ in,
                                                      const int* __restrict__ tgt,
                                                      float* __restrict__ out) {
    __shared__ float s_int[4][NC];      // per-warp inter bins (4 warps)
    __shared__ float s_blk[NACC];
    __shared__ bool s_last;
    for (int t = threadIdx.x; t < NACC; t += MBT) s_blk[t] = 0.0f;
    for (int t = threadIdx.x; t < 4 * NC; t += MBT) ((float*)s_int)[t] = 0.0f;
    __syncthreads();

    const int tid = blockIdx.x * MBT + threadIdx.x;
    const int wid = threadIdx.x >> 5;
    const int lane = threadIdx.x & 31;

    const float2* in2 = (const float2*)in;
    const int2* tgt2 = (const int2*)tgt;

    float denom[NC];
#pragma unroll
    for (int c = 0; c < NC; c++) denom[c] = 0.0f;
    float a_focal = 0.0f, a_nll = 0.0f, a_slp = 0.0f, a_bnll = 0.0f;

    Batch A, Bb;

    // prologue: round 0
    load_batch(in2, tgt2, tid, A);

    // steady state: 8 pairs = rounds 0..15 computed, rounds 1..16 prefetched
#pragma unroll 1
    for (int k = 0; k < 8; k++) {
        const int i0 = tid + (2 * k) * NTH;
        load_batch(in2, tgt2, i0 + NTH, Bb);
        compute_batch(A, i0, wid, s_int, denom, a_focal, a_nll, a_slp, a_bnll);
        load_batch(in2, tgt2, i0 + 2 * NTH, A);
        compute_batch(Bb, i0 + NTH, wid, s_int, denom, a_focal, a_nll, a_slp, a_bnll);
    }
    // A holds round 16 (valid for all threads)
    {
        const int i16 = tid + 16 * NTH;
        load_batch(in2, tgt2, i16 + NTH, Bb);           // round 17, valid for all
        compute_batch(A, i16, wid, s_int, denom, a_focal, a_nll, a_slp, a_bnll);

        const int i18 = tid + 18 * NTH;
        const bool v18 = (i18 < NITERS);                // tid < 25600
        load_batch(in2, tgt2, v18 ? i18 : tid, A);      // safe dummy if OOB
        compute_batch(Bb, i16 + NTH, wid, s_int, denom, a_focal, a_nll, a_slp, a_bnll);

        if (v18)
            compute_batch(A, i18, wid, s_int, denom, a_focal, a_nll, a_slp, a_bnll);
    }

    // --- block reduction (4 warps) ---
#pragma unroll
    for (int c = 0; c < NC; c++) {
        float v = warp_sum(denom[c]);
        if (lane == 0) atomicAdd(&s_blk[c], v);
    }
    {
        float v = warp_sum(a_focal);
        if (lane == 0) atomicAdd(&s_blk[38], v);
        v = warp_sum(a_nll);
        if (lane == 0) atomicAdd(&s_blk[39], v);
        v = warp_sum(a_slp);
        if (lane == 0) atomicAdd(&s_blk[40], v);
        v = warp_sum(a_bnll);
        if (lane == 0) atomicAdd(&s_blk[41], v);
    }
    __syncthreads();

    if (threadIdx.x < NC) {
        float vi = s_int[0][threadIdx.x] + s_int[1][threadIdx.x]
                 + s_int[2][threadIdx.x] + s_int[3][threadIdx.x];
        atomicAdd(&g_acc[NC + threadIdx.x], vi);
    }
    if (threadIdx.x < NACC && (threadIdx.x < NC || threadIdx.x >= 38)) {
        atomicAdd(&g_acc[threadIdx.x], s_blk[threadIdx.x]);
    }

    // --- ticketed finalize + state cleanup (graph-replay safe) ---
    __threadfence();
    __syncthreads();
    if (threadIdx.x == 0)
        s_last = (atomicAdd(&g_ticket, 1u) == MAIN_BLOCKS - 1);
    __syncthreads();

    if (s_last && threadIdx.x < 32) {
        const float Ninv = 1.0f / (float)NPIX;
        float ps = (lane < NC) ? g_acc[lane] : 0.0f;
        float it = (lane < NC) ? g_acc[NC + lane] : 0.0f;
        float cn = (lane < NC) ? (float)g_cnt[lane] : 0.0f;
        float d = 0.0f;
        if (lane < NC) d = 1.0f - (2.0f * it + 1e-5f) / (ps + cn + 1e-5f);
        d = warp_sum(d);
        if (lane == 0) {
            float dice = d / (float)NC;
            float focal = g_acc[38] * Ninv;
            float nll_sum = g_acc[39];
            float slp_sum = g_acc[40];
            float ce = (0.9f * nll_sum - 0.1f * slp_sum / (float)NC) * Ninv;
            float boundary = (nll_sum + 0.5f * g_acc[41]) * Ninv;
            out[0] = focal;
            out[1] = dice;
            out[2] = ce;
            out[3] = boundary;
            out[4] = focal + dice + ce + boundary;
        }
        if (lane < NACC) g_acc[lane] = 0.0f;
        if (lane + 32 < NACC) g_acc[lane + 32] = 0.0f;
        if (lane < NC) g_cnt[lane] = 0;
        if (lane == 0) g_ticket = 0u;
    }
}

// ---------------------------------------------------------------------------
extern "C" void kernel_launch(void* const* d_in, const int* in_sizes, int n_in,
                              void* d_out, int out_size) {
    const float* inputs = (const float*)d_in[0];
    const int* targets = (const int*)d_in[1];
    float* out = (float*)d_out;

    diff_kernel<<<DG, DB>>>(targets);
    main_kernel<<<MAIN_BLOCKS, MBT>>>(inputs, targets, out);
}

// round 12
// speedup vs baseline: 1.1151x; 1.1151x over previous
#include <cuda_runtime.h>
#include <cstdint>

#define NB 8
#define NC 19
#define NH 512
#define NW 512
#define HW (NH * NW)            // 262144
#define NPIX (NB * HW)          // 2097152
#define NPAIR (HW / 2)          // 131072 pixel pairs
#define NITERS (NPAIR * NB)     // 1048576 flattened pair-iterations

// g_acc: [0..18] probs_sum_c, [19..37] inter_c, [38] focal [39] nll [40] slp [41] bnll
#define NACC 42

__device__ float g_acc[NACC];
__device__ int g_cnt[NC];
__device__ unsigned int g_ticket;
__device__ unsigned char g_diff[HW];

// ---------------------------------------------------------------------------
#define DB 128
#define DG ((HW / 4) / DB)      // 512 blocks

__global__ __launch_bounds__(DB) void diff_kernel(const int* __restrict__ tgt) {
    __shared__ unsigned int s_h[DB][NC];
#pragma unroll
    for (int c = 0; c < NC; c++) s_h[threadIdx.x][c] = 0u;

    const int idx = blockIdx.x * DB + threadIdx.x;      // over HW/4
    const int h = idx >> 7;
    const bool interior = (h >= 1) && (h <= NH - 2);
    const int4* t4 = (const int4*)tgt;

    uchar4 d = make_uchar4(0, 0, 0, 0);
#pragma unroll
    for (int b = 0; b < NB; b++) {
        int base = b * (HW / 4) + idx;
        int4 m = __ldg(t4 + base);
        s_h[threadIdx.x][m.x]++;
        s_h[threadIdx.x][m.y]++;
        s_h[threadIdx.x][m.z]++;
        s_h[threadIdx.x][m.w]++;
        if (interior) {
            int4 a = __ldg(t4 + base - NW / 4);
            int4 q = __ldg(t4 + base + NW / 4);
            d.x |= (unsigned char)((a.x != m.x) | (a.x != q.x));
            d.y |= (unsigned char)((a.y != m.y) | (a.y != q.y));
            d.z |= (unsigned char)((a.z != m.z) | (a.z != q.z));
            d.w |= (unsigned char)((a.w != m.w) | (a.w != q.w));
        }
    }
    ((uchar4*)g_diff)[idx] = d;

    __syncthreads();
    if (threadIdx.x < NC) {
        unsigned int s = 0;
#pragma unroll 8
        for (int r = 0; r < DB; r++) s += s_h[r][threadIdx.x];
        atomicAdd(&g_cnt[threadIdx.x], (int)s);
    }
}

// ---------------------------------------------------------------------------
__device__ __forceinline__ float warp_sum(float v) {
#pragma unroll
    for (int o = 16; o; o >>= 1) v += __shfl_down_sync(0xffffffffu, v, o);
    return v;
}

// ---------------------------------------------------------------------------
// Persistent single-wave grid, smem-staged target select.
#define MBT 128
#define MAIN_BLOCKS 740              // 5 CTAs/SM * 148 SMs, single wave
#define NTH (MAIN_BLOCKS * MBT)      // 94720 threads

__global__ __launch_bounds__(MBT, 5) void main_kernel(const float* __restrict__ in,
                                                      const int* __restrict__ tgt,
                                                      float* __restrict__ out) {
    __shared__ float2 s_x[NC][MBT];     // per-thread staging of raw logits (19.4 KB)
    __shared__ float s_int[4][NC];      // per-warp inter bins
    __shared__ float s_blk[NACC];
    __shared__ bool s_last;
    for (int t = threadIdx.x; t < NACC; t += MBT) s_blk[t] = 0.0f;
    for (int t = threadIdx.x; t < 4 * NC; t += MBT) ((float*)s_int)[t] = 0.0f;
    __syncthreads();

    const int tid = blockIdx.x * MBT + threadIdx.x;
    const int wid = threadIdx.x >> 5;
    const int lane = threadIdx.x & 31;

    const float2* in2 = (const float2*)in;
    const int2* tgt2 = (const int2*)tgt;

    float denom[NC];
#pragma unroll
    for (int c = 0; c < NC; c++) denom[c] = 0.0f;
    float a_focal = 0.0f, a_nll = 0.0f, a_slp = 0.0f, a_bnll = 0.0f;

#pragma unroll 1
    for (int idx = tid; idx < NITERS; idx += NTH) {
        const int pair = idx & (NPAIR - 1);
        const int b = idx >> 17;               // NPAIR == 2^17

        // boundary flags (g_diff is 256 KB, L2-resident)
        const int hw0 = 2 * pair;
        const int h = hw0 >> 9;
        const int w0 = hw0 & (NW - 1);
        float bm0 = 0.0f, bm1 = 0.0f;
        if (h >= 1 && h <= NH - 2) {
            unsigned char dm = g_diff[hw0];
            unsigned char dp = g_diff[hw0 + 1];
            if (w0 >= 1) bm0 = (float)(g_diff[hw0 - 1] | dm | dp);
            if (w0 + 1 <= NW - 2) bm1 = (float)(dm | dp | g_diff[hw0 + 2]);
        }

        const int2 tt = __ldg(tgt2 + b * (HW / 2) + pair);
        const int t0 = tt.x, t1 = tt.y;
        const float2* base = in2 + (size_t)b * (NC * (HW / 2)) + pair;

        // load 19 float2; stage raw logits to smem (no SEL chains, x transient)
        float2 e[NC];
        float sA0 = 0.f, sB0 = 0.f, sA1 = 0.f, sB1 = 0.f;
        float zA0 = 0.f, zB0 = 0.f, zA1 = 0.f, zB1 = 0.f;
#pragma unroll
        for (int c = 0; c < NC; c++) {
            float2 v = __ldg(base + (size_t)c * (HW / 2));
            s_x[c][threadIdx.x] = v;
            float ex = __expf(v.x);
            float ey = __expf(v.y);
            if (c & 1) { sB0 += v.x; sB1 += v.y; zB0 += ex; zB1 += ey; }
            else       { sA0 += v.x; sA1 += v.y; zA0 += ex; zA1 += ey; }
            e[c].x = ex; e[c].y = ey;
        }
        const float sumx0 = sA0 + sB0, sumx1 = sA1 + sB1;
        const float Z0 = zA0 + zB0, Z1 = zA1 + zB1;

        // target logits: 2 indexed LDS from this thread's own staging slots
        const float xt0 = s_x[t0][threadIdx.x].x;
        const float xt1 = s_x[t1][threadIdx.x].y;

        const float invZ0 = __fdividef(1.0f, Z0);
        const float invZ1 = __fdividef(1.0f, Z1);
        const float logZ0 = __logf(Z0);
        const float logZ1 = __logf(Z1);
        const float nll0 = logZ0 - xt0;
        const float nll1 = logZ1 - xt1;
        const float pt0 = __expf(xt0) * invZ0;
        const float pt1 = __expf(xt1) * invZ1;

#pragma unroll
        for (int c = 0; c < NC; c++) {
            denom[c] = fmaf(e[c].x, invZ0, fmaf(e[c].y, invZ1, denom[c]));
        }

        const float om0 = 1.0f - pt0, om1 = 1.0f - pt1;
        a_focal = fmaf(om0 * om0, nll0, fmaf(om1 * om1, nll1, a_focal));
        a_nll += nll0 + nll1;
        a_slp += (sumx0 + sumx1) - (float)NC * (logZ0 + logZ1);
        a_bnll = fmaf(nll0, bm0, fmaf(nll1, bm1, a_bnll));

        atomicAdd(&s_int[wid][t0], pt0);
        atomicAdd(&s_int[wid][t1], pt1);
    }

    // --- block reduction (4 warps) ---
#pragma unroll
    for (int c = 0; c < NC; c++) {
        float v = warp_sum(denom[c]);
        if (lane == 0) atomicAdd(&s_blk[c], v);
    }
    {
        float v = warp_sum(a_focal);
        if (lane == 0) atomicAdd(&s_blk[38], v);
        v = warp_sum(a_nll);
        if (lane == 0) atomicAdd(&s_blk[39], v);
        v = warp_sum(a_slp);
        if (lane == 0) atomicAdd(&s_blk[40], v);
        v = warp_sum(a_bnll);
        if (lane == 0) atomicAdd(&s_blk[41], v);
    }
    __syncthreads();

    if (threadIdx.x < NC) {
        float vi = s_int[0][threadIdx.x] + s_int[1][threadIdx.x]
                 + s_int[2][threadIdx.x] + s_int[3][threadIdx.x];
        atomicAdd(&g_acc[NC + threadIdx.x], vi);
    }
    if (threadIdx.x < NACC && (threadIdx.x < NC || threadIdx.x >= 38)) {
        atomicAdd(&g_acc[threadIdx.x], s_blk[threadIdx.x]);
    }

    // --- ticketed finalize + state cleanup (graph-replay safe) ---
    __threadfence();
    __syncthreads();
    if (threadIdx.x == 0)
        s_last = (atomicAdd(&g_ticket, 1u) == MAIN_BLOCKS - 1);
    __syncthreads();

    if (s_last && threadIdx.x < 32) {
        const float Ninv = 1.0f / (float)NPIX;
        float ps = (lane < NC) ? g_acc[lane] : 0.0f;
        float it = (lane < NC) ? g_acc[NC + lane] : 0.0f;
        float cn = (lane < NC) ? (float)g_cnt[lane] : 0.0f;
        float d = 0.0f;
        if (lane < NC) d = 1.0f - (2.0f * it + 1e-5f) / (ps + cn + 1e-5f);
        d = warp_sum(d);
        if (lane == 0) {
            float dice = d / (float)NC;
            float focal = g_acc[38] * Ninv;
            float nll_sum = g_acc[39];
            float slp_sum = g_acc[40];
            float ce = (0.9f * nll_sum - 0.1f * slp_sum / (float)NC) * Ninv;
            float boundary = (nll_sum + 0.5f * g_acc[41]) * Ninv;
            out[0] = focal;
            out[1] = dice;
            out[2] = ce;
            out[3] = boundary;
            out[4] = focal + dice + ce + boundary;
        }
        if (lane < NACC) g_acc[lane] = 0.0f;
        if (lane + 32 < NACC) g_acc[lane + 32] = 0.0f;
        if (lane < NC) g_cnt[lane] = 0;
        if (lane == 0) g_ticket = 0u;
    }
}

// ---------------------------------------------------------------------------
extern "C" void kernel_launch(void* const* d_in, const int* in_sizes, int n_in,
                              void* d_out, int out_size) {
    const float* inputs = (const float*)d_in[0];
    const int* targets = (const int*)d_in[1];
    float* out = (float*)d_out;

    diff_kernel<<<DG, DB>>>(targets);
    main_kernel<<<MAIN_BLOCKS, MBT>>>(inputs, targets, out);
}